// round 1
// baseline (speedup 1.0000x reference)
#include <cuda_runtime.h>
#include <cstdint>
#include <cstddef>

#define D    4096
#define NH   32
#define H    128
#define S    4096
#define KMASK (-2.3819763e+38f)

// ---------------- scratch (device globals; no allocation allowed) ----------
__device__ __align__(16) float g_qkvp[16 * 96 * 128];   // qkv gemv partials
__device__ __align__(16) float g_q[NH * H];             // rope'd + scaled q
__device__ __align__(16) float g_knew[NH * H];          // rope'd new k row
__device__ __align__(16) float g_vnew[NH * H];          // new v row
__device__ __align__(16) float g_logits[NH * S];
__device__ __align__(16) float g_probs[NH * S];
__device__ __align__(16) float g_encpart[32 * NH * H];  // [chunk][n*H+h]
__device__ __align__(16) float g_enc[NH * H];
__device__ __align__(16) float g_opart[8 * D];          // [nh-chunk][d]

// ---------------- K1: qkv = x @ w_qkv, partial over D ----------------------
// grid (96, 4): blockIdx.x = s*32+n, blockIdx.y = D-chunk of 1024
// block 128: tid%32 = float4 group over h (4 h each), tid/32 = d-slice of 256
__global__ void __launch_bounds__(128) k_qkv_partial(const float* __restrict__ x,
                                                     const float* __restrict__ w) {
    int sn = blockIdx.x;
    int dchunk = blockIdx.y;
    int tid = threadIdx.x;
    int hv = tid & 31;
    int ds = tid >> 5;

    __shared__ float xs[1024];
    int dbase = dchunk * 1024;
    for (int i = tid; i < 1024; i += 128) xs[i] = x[dbase + i];
    __syncthreads();

    const float4* wv = (const float4*)(w + (size_t)sn * D * H + (size_t)dbase * H);
    float4 acc = make_float4(0.f, 0.f, 0.f, 0.f);
    int d0 = ds * 256;
#pragma unroll 4
    for (int d = d0; d < d0 + 256; ++d) {
        float xv = xs[d];
        float4 wq = wv[d * 32 + hv];
        acc.x += xv * wq.x; acc.y += xv * wq.y;
        acc.z += xv * wq.z; acc.w += xv * wq.w;
    }
    int p = dchunk * 4 + ds;                      // 0..15
    ((float4*)g_qkvp)[((size_t)p * 96 + sn) * 32 + hv] = acc;
}

// ---------------- K2: reduce partials, RoPE, scatter new rows --------------
// grid 96 (s*32+n), block 128 (h)
__global__ void __launch_bounds__(128) k_qkv_rope(const int* __restrict__ segp,
                                                  const int* __restrict__ tsp,
                                                  float* __restrict__ k_out,
                                                  float* __restrict__ v_out) {
    int sn = blockIdx.x;
    int h = threadIdx.x;
    int s = sn >> 5, n = sn & 31;

    float val = 0.f;
#pragma unroll
    for (int p = 0; p < 16; ++p) val += g_qkvp[((size_t)p * 96 + sn) * 128 + h];

    __shared__ float sm[128];
    sm[h] = val;
    __syncthreads();

    int ts = tsp[0];
    if (s == 2) {
        g_vnew[n * 128 + h] = val;
        v_out[((size_t)ts * NH + n) * H + h] = val;
        return;
    }
    float pos = (float)segp[0];
    int i = h & 63;
    float timescale = powf(10000.f, (float)i * (1.f / 64.f));
    float ang = pos / timescale;
    float sn_, cs;
    sincosf(ang, &sn_, &cs);
    float out;
    if (h < 64) out = sm[h] * cs - sm[h + 64] * sn_;
    else        out = sm[h] * cs + sm[h - 64] * sn_;
    if (s == 0) {
        g_q[n * 128 + h] = out * 0.08838834764831845f;  // head_dim^-0.5
    } else {
        g_knew[n * 128 + h] = out;
        k_out[((size_t)ts * NH + n) * H + h] = out;
    }
}

// ---------------- K3: logits + k-cache copy --------------------------------
// grid (S/8, NH), block 256 = 8 warps; each warp does one (s, n) row of 128
__global__ void __launch_bounds__(256) k_logits_kcopy(const float* __restrict__ k_in,
                                                      const float* __restrict__ mask,
                                                      const int* __restrict__ tsp,
                                                      float* __restrict__ k_out) {
    int warp = threadIdx.x >> 5;
    int lane = threadIdx.x & 31;
    int s = blockIdx.x * 8 + warp;
    int n = blockIdx.y;
    int ts = tsp[0];

    size_t ridx = (((size_t)s * NH + n) * H) >> 2;  // float4 index of row start
    float4 kk;
    if (s == ts) {
        kk = ((const float4*)g_knew)[n * 32 + lane];
    } else {
        kk = ((const float4*)k_in)[ridx + lane];
        ((float4*)k_out)[ridx + lane] = kk;
    }
    float4 qq = ((const float4*)g_q)[n * 32 + lane];
    float dot = kk.x * qq.x + kk.y * qq.y + kk.z * qq.z + kk.w * qq.w;
#pragma unroll
    for (int off = 16; off; off >>= 1)
        dot += __shfl_xor_sync(0xffffffffu, dot, off);
    if (lane == 0) {
        float m = mask[s];
        g_logits[(size_t)n * S + s] = (m >= 0.5f * KMASK) ? dot : KMASK;
    }
}

// ---------------- K4: softmax per head -------------------------------------
__global__ void __launch_bounds__(256) k_softmax() {
    int n = blockIdx.x;
    int t = threadIdx.x;
    __shared__ float red[256];

    float m = -3.4e38f;
    for (int s = t; s < S; s += 256) m = fmaxf(m, g_logits[(size_t)n * S + s]);
    red[t] = m; __syncthreads();
    for (int o = 128; o; o >>= 1) { if (t < o) red[t] = fmaxf(red[t], red[t + o]); __syncthreads(); }
    float mx = red[0];
    __syncthreads();

    float sum = 0.f;
    for (int s = t; s < S; s += 256) {
        float e = expf(g_logits[(size_t)n * S + s] - mx);
        g_probs[(size_t)n * S + s] = e;
        sum += e;
    }
    red[t] = sum; __syncthreads();
    for (int o = 128; o; o >>= 1) { if (t < o) red[t] += red[t + o]; __syncthreads(); }
    float inv = 1.f / red[0];
    for (int s = t; s < S; s += 256) g_probs[(size_t)n * S + s] *= inv;
}

// ---------------- K5: encoded partials + v-cache copy ----------------------
// grid (32 s-chunks of 128, NH), block 128 (h)
__global__ void __launch_bounds__(128) k_enc_partial(const float* __restrict__ v_in,
                                                     const int* __restrict__ tsp,
                                                     float* __restrict__ v_out) {
    int c = blockIdx.x;
    int n = blockIdx.y;
    int h = threadIdx.x;
    int ts = tsp[0];

    float acc = 0.f;
    int s0 = c * 128;
#pragma unroll 4
    for (int s = s0; s < s0 + 128; ++s) {
        float vv;
        size_t idx = ((size_t)s * NH + n) * H + h;
        if (s == ts) {
            vv = g_vnew[n * 128 + h];
        } else {
            vv = v_in[idx];
            v_out[idx] = vv;
        }
        acc += g_probs[(size_t)n * S + s] * vv;
    }
    g_encpart[((size_t)c * NH + n) * H + h] = acc;
}

// ---------------- K6: reduce encoded partials ------------------------------
__global__ void __launch_bounds__(128) k_enc_reduce() {
    int idx = blockIdx.x * 128 + threadIdx.x;   // 0..4095
    float v = 0.f;
#pragma unroll
    for (int c = 0; c < 32; ++c) v += g_encpart[(size_t)c * NH * H + idx];
    g_enc[idx] = v;
}

// ---------------- K7: output GEMV partials ---------------------------------
// grid (32 d-tiles of 128, 8 nh-chunks of 512), block 128
__global__ void __launch_bounds__(128) k_out_partial(const float* __restrict__ w_out) {
    int d = blockIdx.x * 128 + threadIdx.x;
    int nh0 = blockIdx.y * 512;
    float acc = 0.f;
#pragma unroll 8
    for (int nh = nh0; nh < nh0 + 512; ++nh)
        acc += g_enc[nh] * w_out[(size_t)nh * D + d];
    g_opart[(size_t)blockIdx.y * D + d] = acc;
}

// ---------------- K8: final output reduce ----------------------------------
__global__ void __launch_bounds__(128) k_out_reduce(float* __restrict__ attn) {
    int d = blockIdx.x * 128 + threadIdx.x;
    float v = 0.f;
#pragma unroll
    for (int c = 0; c < 8; ++c) v += g_opart[(size_t)c * D + d];
    attn[d] = v;
}

// ---------------- launch ----------------------------------------------------
extern "C" void kernel_launch(void* const* d_in, const int* in_sizes, int n_in,
                              void* d_out, int out_size) {
    const float* x      = (const float*)d_in[0];
    const float* w_qkv  = (const float*)d_in[1];
    const float* w_out  = (const float*)d_in[2];
    const float* k_in   = (const float*)d_in[3];
    const float* v_in   = (const float*)d_in[4];
    const float* mask   = (const float*)d_in[5];
    const int*   segp   = (const int*)d_in[6];
    const int*   tsp    = (const int*)d_in[7];

    float* out   = (float*)d_out;
    float* k_out = out;
    float* v_out = out + (size_t)S * NH * H;
    float* attn  = out + 2ull * S * NH * H;

    k_qkv_partial<<<dim3(96, 4), 128>>>(x, w_qkv);
    k_qkv_rope<<<96, 128>>>(segp, tsp, k_out, v_out);
    k_logits_kcopy<<<dim3(S / 8, NH), 256>>>(k_in, mask, tsp, k_out);
    k_softmax<<<NH, 256>>>();
    k_enc_partial<<<dim3(32, NH), 128>>>(v_in, tsp, v_out);
    k_enc_reduce<<<32, 128>>>();
    k_out_partial<<<dim3(32, 8), 128>>>(w_out);
    k_out_reduce<<<32, 128>>>(attn);
}

// round 2
// speedup vs baseline: 1.2002x; 1.2002x over previous
#include <cuda_runtime.h>
#include <cstdint>
#include <cstddef>

#define D    4096
#define NH   32
#define H    128
#define S    4096
#define KMASK (-2.3819763e+38f)

// ---------------- scratch (device globals; no allocation allowed) ----------
__device__ __align__(16) float g_qkvp[16 * 96 * 128];   // qkv gemv partials
__device__ __align__(16) float g_q[NH * H];             // rope'd + scaled q
__device__ __align__(16) float g_knew[NH * H];          // rope'd new k row
__device__ __align__(16) float g_vnew[NH * H];          // new v row
__device__ __align__(16) float g_logits[NH * S];
__device__ float g_mx[NH];
__device__ float g_inv[NH];
__device__ __align__(16) float g_encpart[32 * NH * H];  // [chunk][n*H+h]
__device__ __align__(16) float g_enc[NH * H];
__device__ __align__(16) float g_opart[32 * D];         // [nh-chunk][d]

// ---------------- K1: qkv = x @ w_qkv, partial over D ----------------------
// grid (96, 4): blockIdx.x = s*32+n, blockIdx.y = D-chunk of 1024
// block 128: tid%32 = float4 group over h (4 h each), tid/32 = d-slice of 256
__global__ void __launch_bounds__(128) k_qkv_partial(const float* __restrict__ x,
                                                     const float* __restrict__ w) {
    int sn = blockIdx.x;
    int dchunk = blockIdx.y;
    int tid = threadIdx.x;
    int hv = tid & 31;
    int ds = tid >> 5;

    __shared__ float xs[1024];
    int dbase = dchunk * 1024;
    for (int i = tid; i < 1024; i += 128) xs[i] = x[dbase + i];
    __syncthreads();

    const float4* wv = (const float4*)(w + (size_t)sn * D * H + (size_t)dbase * H);
    float4 acc = make_float4(0.f, 0.f, 0.f, 0.f);
    int d0 = ds * 256;
#pragma unroll 8
    for (int d = d0; d < d0 + 256; ++d) {
        float xv = xs[d];
        float4 wq = wv[d * 32 + hv];
        acc.x += xv * wq.x; acc.y += xv * wq.y;
        acc.z += xv * wq.z; acc.w += xv * wq.w;
    }
    int p = dchunk * 4 + ds;                      // 0..15
    ((float4*)g_qkvp)[((size_t)p * 96 + sn) * 32 + hv] = acc;
}

// ---------------- K2: reduce partials, RoPE, scatter new rows --------------
// grid 96 (s*32+n), block 128 (h)
__global__ void __launch_bounds__(128) k_qkv_rope(const int* __restrict__ segp,
                                                  const int* __restrict__ tsp,
                                                  float* __restrict__ k_out,
                                                  float* __restrict__ v_out) {
    int sn = blockIdx.x;
    int h = threadIdx.x;
    int s = sn >> 5, n = sn & 31;

    float val = 0.f;
#pragma unroll
    for (int p = 0; p < 16; ++p) val += g_qkvp[((size_t)p * 96 + sn) * 128 + h];

    __shared__ float sm[128];
    sm[h] = val;
    __syncthreads();

    int ts = tsp[0];
    if (s == 2) {
        g_vnew[n * 128 + h] = val;
        v_out[((size_t)ts * NH + n) * H + h] = val;
        return;
    }
    float pos = (float)segp[0];
    int i = h & 63;
    float timescale = powf(10000.f, (float)i * (1.f / 64.f));
    float ang = pos / timescale;
    float sn_, cs;
    sincosf(ang, &sn_, &cs);
    float out;
    if (h < 64) out = sm[h] * cs - sm[h + 64] * sn_;
    else        out = sm[h] * cs + sm[h - 64] * sn_;
    if (s == 0) {
        g_q[n * 128 + h] = out * 0.08838834764831845f;  // head_dim^-0.5
    } else {
        g_knew[n * 128 + h] = out;
        k_out[((size_t)ts * NH + n) * H + h] = out;
    }
}

// ---------------- K3: logits + k-cache copy --------------------------------
// grid (S/8, NH), block 256 = 8 warps; each warp does one (s, n) row of 128
__global__ void __launch_bounds__(256) k_logits_kcopy(const float* __restrict__ k_in,
                                                      const float* __restrict__ mask,
                                                      const int* __restrict__ tsp,
                                                      float* __restrict__ k_out) {
    int warp = threadIdx.x >> 5;
    int lane = threadIdx.x & 31;
    int s = blockIdx.x * 8 + warp;
    int n = blockIdx.y;
    int ts = tsp[0];

    size_t ridx = (((size_t)s * NH + n) * H) >> 2;  // float4 index of row start
    float4 kk;
    if (s == ts) {
        kk = ((const float4*)g_knew)[n * 32 + lane];
    } else {
        kk = ((const float4*)k_in)[ridx + lane];
        ((float4*)k_out)[ridx + lane] = kk;
    }
    float4 qq = ((const float4*)g_q)[n * 32 + lane];
    float dot = kk.x * qq.x + kk.y * qq.y + kk.z * qq.z + kk.w * qq.w;
#pragma unroll
    for (int off = 16; off; off >>= 1)
        dot += __shfl_xor_sync(0xffffffffu, dot, off);
    if (lane == 0) {
        float m = mask[s];
        g_logits[(size_t)n * S + s] = (m >= 0.5f * KMASK) ? dot : KMASK;
    }
}

// ---------------- K4: single-pass online softmax stats per head -----------
// grid NH, block 1024; produces g_mx[n], g_inv[n] = 1/sum(exp(l-mx))
__global__ void __launch_bounds__(1024) k_softmax_stats() {
    int n = blockIdx.x;
    int t = threadIdx.x;
    __shared__ float sm_m[1024];
    __shared__ float sm_l[1024];

    float m = -3.4e38f, l = 0.f;
    const float* lg = g_logits + (size_t)n * S;
#pragma unroll 4
    for (int s = t; s < S; s += 1024) {
        float v = lg[s];
        float nm = fmaxf(m, v);
        l = l * __expf(m - nm) + __expf(v - nm);
        m = nm;
    }
    sm_m[t] = m; sm_l[t] = l;
    __syncthreads();
    for (int o = 512; o; o >>= 1) {
        if (t < o) {
            float m2 = sm_m[t + o], l2 = sm_l[t + o];
            float nm = fmaxf(sm_m[t], m2);
            sm_l[t] = sm_l[t] * __expf(sm_m[t] - nm) + l2 * __expf(m2 - nm);
            sm_m[t] = nm;
        }
        __syncthreads();
    }
    if (t == 0) {
        g_mx[n] = sm_m[0];
        g_inv[n] = 1.f / sm_l[0];
    }
}

// ---------------- K5: encoded partials + v-cache copy (vectorized) ---------
// grid (32 s-chunks of 128, NH), block 256 = 8 warps; warp handles 16 s rows
// lane owns float4 over h (4 h). prob computed inline from logits + stats.
__global__ void __launch_bounds__(256) k_enc_partial(const float* __restrict__ v_in,
                                                     const int* __restrict__ tsp,
                                                     float* __restrict__ v_out) {
    int c = blockIdx.x;
    int n = blockIdx.y;
    int warp = threadIdx.x >> 5;
    int lane = threadIdx.x & 31;
    int ts = tsp[0];
    float mx = g_mx[n], inv = g_inv[n];
    const float* lg = g_logits + (size_t)n * S;

    float4 acc = make_float4(0.f, 0.f, 0.f, 0.f);
    int s0 = c * 128 + warp;
#pragma unroll 4
    for (int i = 0; i < 16; ++i) {
        int s = s0 + i * 8;
        size_t ridx = (((size_t)s * NH + n) * H) >> 2;
        float4 vv;
        if (s == ts) {
            vv = ((const float4*)g_vnew)[n * 32 + lane];
        } else {
            vv = ((const float4*)v_in)[ridx + lane];
            ((float4*)v_out)[ridx + lane] = vv;
        }
        float p = __expf(lg[s] - mx) * inv;
        acc.x += p * vv.x; acc.y += p * vv.y;
        acc.z += p * vv.z; acc.w += p * vv.w;
    }

    __shared__ float4 red[8][32];
    red[warp][lane] = acc;
    __syncthreads();
    if (warp == 0) {
        float4 t = red[0][lane];
#pragma unroll
        for (int w = 1; w < 8; ++w) {
            float4 o = red[w][lane];
            t.x += o.x; t.y += o.y; t.z += o.z; t.w += o.w;
        }
        ((float4*)g_encpart)[((size_t)c * NH + n) * 32 + lane] = t;
    }
}

// ---------------- K6: reduce encoded partials ------------------------------
__global__ void __launch_bounds__(128) k_enc_reduce() {
    int idx = blockIdx.x * 128 + threadIdx.x;   // 0..4095
    float v = 0.f;
#pragma unroll
    for (int c = 0; c < 32; ++c) v += g_encpart[(size_t)c * NH * H + idx];
    g_enc[idx] = v;
}

// ---------------- K7: output GEMV partials (vectorized) --------------------
// grid (8 d-tiles of 512, 32 nh-chunks of 128), block 128: thread owns 4 d
__global__ void __launch_bounds__(128) k_out_partial(const float* __restrict__ w_out) {
    int d4 = (blockIdx.x * 512 + threadIdx.x * 4) >> 2;   // float4 index in d
    int nh0 = blockIdx.y * 128;
    const float4* wv = (const float4*)w_out;
    float4 acc = make_float4(0.f, 0.f, 0.f, 0.f);
#pragma unroll 8
    for (int nh = nh0; nh < nh0 + 128; ++nh) {
        float e = g_enc[nh];
        float4 w4 = wv[(size_t)nh * (D / 4) + d4];
        acc.x += e * w4.x; acc.y += e * w4.y;
        acc.z += e * w4.z; acc.w += e * w4.w;
    }
    ((float4*)g_opart)[(size_t)blockIdx.y * (D / 4) + d4] = acc;
}

// ---------------- K8: final output reduce ----------------------------------
__global__ void __launch_bounds__(128) k_out_reduce(float* __restrict__ attn) {
    int d = blockIdx.x * 128 + threadIdx.x;
    float v = 0.f;
#pragma unroll
    for (int c = 0; c < 32; ++c) v += g_opart[(size_t)c * D + d];
    attn[d] = v;
}

// ---------------- launch ----------------------------------------------------
extern "C" void kernel_launch(void* const* d_in, const int* in_sizes, int n_in,
                              void* d_out, int out_size) {
    const float* x      = (const float*)d_in[0];
    const float* w_qkv  = (const float*)d_in[1];
    const float* w_out  = (const float*)d_in[2];
    const float* k_in   = (const float*)d_in[3];
    const float* v_in   = (const float*)d_in[4];
    const float* mask   = (const float*)d_in[5];
    const int*   segp   = (const int*)d_in[6];
    const int*   tsp    = (const int*)d_in[7];

    float* out   = (float*)d_out;
    float* k_out = out;
    float* v_out = out + (size_t)S * NH * H;
    float* attn  = out + 2ull * S * NH * H;

    k_qkv_partial<<<dim3(96, 4), 128>>>(x, w_qkv);
    k_qkv_rope<<<96, 128>>>(segp, tsp, k_out, v_out);
    k_logits_kcopy<<<dim3(S / 8, NH), 256>>>(k_in, mask, tsp, k_out);
    k_softmax_stats<<<NH, 1024>>>();
    k_enc_partial<<<dim3(32, NH), 256>>>(v_in, tsp, v_out);
    k_enc_reduce<<<32, 128>>>();
    k_out_partial<<<dim3(8, 32), 128>>>(w_out);
    k_out_reduce<<<32, 128>>>(attn);
}

// round 3
// speedup vs baseline: 1.5520x; 1.2931x over previous
#include <cuda_runtime.h>
#include <cstdint>
#include <cstddef>

#define D    4096
#define NH   32
#define H    128
#define S    4096
#define KMASK (-2.3819763e+38f)

// ---------------- scratch (device globals; no allocation allowed) ----------
__device__ __align__(16) float g_qkvp[64 * 96 * 128];   // qkv gemv partials
__device__ __align__(16) float g_q[NH * H];             // rope'd + scaled q
__device__ __align__(16) float g_knew[NH * H];          // rope'd new k row
__device__ __align__(16) float g_vnew[NH * H];          // new v row
__device__ __align__(16) float g_logits[NH * S];
__device__ float g_pm[NH * 64];                         // per-block partial max
__device__ float g_pl[NH * 64];                         // per-block partial sum
__device__ float g_mx[NH];
__device__ float g_inv[NH];
__device__ __align__(16) float g_encpart[32 * NH * H];  // [chunk][nh]
__device__ __align__(16) float g_opart[64 * D];         // [nh-chunk][d]

// ---------------- K1: qkv = x @ w_qkv, partial over D ----------------------
// grid (96, 16): blockIdx.x = s*32+n, blockIdx.y = D-chunk of 256
// block 128: tid%32 = float4 group over h, tid/32 = d-slice of 64
__global__ void __launch_bounds__(128) k_qkv_partial(const float* __restrict__ x,
                                                     const float* __restrict__ w) {
    int sn = blockIdx.x;
    int dchunk = blockIdx.y;
    int tid = threadIdx.x;
    int hv = tid & 31;
    int ds = tid >> 5;

    __shared__ float xs[256];
    int dbase = dchunk * 256;
    if (tid < 256 - 128) {}  // keep 128-thread fill below
    for (int i = tid; i < 256; i += 128) xs[i] = x[dbase + i];
    __syncthreads();

    const float4* wv = (const float4*)(w + (size_t)sn * D * H + (size_t)dbase * H);
    float4 acc = make_float4(0.f, 0.f, 0.f, 0.f);
    int d0 = ds * 64;
#pragma unroll 8
    for (int d = d0; d < d0 + 64; ++d) {
        float xv = xs[d];
        float4 wq = wv[d * 32 + hv];
        acc.x += xv * wq.x; acc.y += xv * wq.y;
        acc.z += xv * wq.z; acc.w += xv * wq.w;
    }
    int p = dchunk * 4 + ds;                      // 0..63
    ((float4*)g_qkvp)[((size_t)p * 96 + sn) * 32 + hv] = acc;
}

// ---------------- K2: reduce partials, RoPE, scatter new rows --------------
__global__ void __launch_bounds__(128) k_qkv_rope(const int* __restrict__ segp,
                                                  const int* __restrict__ tsp,
                                                  float* __restrict__ k_out,
                                                  float* __restrict__ v_out) {
    int sn = blockIdx.x;
    int h = threadIdx.x;
    int s = sn >> 5, n = sn & 31;

    float val = 0.f;
#pragma unroll
    for (int p = 0; p < 64; ++p) val += g_qkvp[((size_t)p * 96 + sn) * 128 + h];

    __shared__ float sm[128];
    sm[h] = val;
    __syncthreads();

    int ts = tsp[0];
    if (s == 2) {
        g_vnew[n * 128 + h] = val;
        v_out[((size_t)ts * NH + n) * H + h] = val;
        return;
    }
    float pos = (float)segp[0];
    int i = h & 63;
    float timescale = powf(10000.f, (float)i * (1.f / 64.f));
    float ang = pos / timescale;
    float sn_, cs;
    sincosf(ang, &sn_, &cs);
    float out;
    if (h < 64) out = sm[h] * cs - sm[h + 64] * sn_;
    else        out = sm[h] * cs + sm[h - 64] * sn_;
    if (s == 0) {
        g_q[n * 128 + h] = out * 0.08838834764831845f;  // head_dim^-0.5
    } else {
        g_knew[n * 128 + h] = out;
        k_out[((size_t)ts * NH + n) * H + h] = out;
    }
}

// ---------------- K3: logits + k-cache copy + partial softmax stats --------
// grid (S/64, NH), block 256 = 8 warps; each warp does 8 (s,n) rows
__global__ void __launch_bounds__(256) k_logits_kcopy(const float* __restrict__ k_in,
                                                      const float* __restrict__ mask,
                                                      const int* __restrict__ tsp,
                                                      float* __restrict__ k_out) {
    int warp = threadIdx.x >> 5;
    int lane = threadIdx.x & 31;
    int n = blockIdx.y;
    int s0 = blockIdx.x * 64 + warp * 8;
    int ts = tsp[0];

    float4 qq = ((const float4*)g_q)[n * 32 + lane];

    // front-batched loads (MLP 8)
    float4 kk[8];
#pragma unroll
    for (int i = 0; i < 8; ++i) {
        int s = s0 + i;
        size_t ridx = (((size_t)s * NH + n) * H) >> 2;
        kk[i] = (s == ts) ? ((const float4*)g_knew)[n * 32 + lane]
                          : ((const float4*)k_in)[ridx + lane];
    }
#pragma unroll
    for (int i = 0; i < 8; ++i) {
        int s = s0 + i;
        if (s != ts) {
            size_t ridx = (((size_t)s * NH + n) * H) >> 2;
            ((float4*)k_out)[ridx + lane] = kk[i];
        }
    }

    float m = -3.4e38f, l = 0.f;
#pragma unroll
    for (int i = 0; i < 8; ++i) {
        int s = s0 + i;
        float dot = kk[i].x * qq.x + kk[i].y * qq.y + kk[i].z * qq.z + kk[i].w * qq.w;
#pragma unroll
        for (int off = 16; off; off >>= 1)
            dot += __shfl_xor_sync(0xffffffffu, dot, off);
        float lg = (mask[s] >= 0.5f * KMASK) ? dot : KMASK;
        if (lane == 0) g_logits[(size_t)n * S + s] = lg;
        float nm = fmaxf(m, lg);
        l = l * __expf(m - nm) + __expf(lg - nm);
        m = nm;
    }

    // block-level merge of 8 per-warp (m,l)
    __shared__ float sm_m[8], sm_l[8];
    if (lane == 0) { sm_m[warp] = m; sm_l[warp] = l; }
    __syncthreads();
    if (threadIdx.x == 0) {
        float bm = sm_m[0], bl = sm_l[0];
#pragma unroll
        for (int w = 1; w < 8; ++w) {
            float nm = fmaxf(bm, sm_m[w]);
            bl = bl * __expf(bm - nm) + sm_l[w] * __expf(sm_m[w] - nm);
            bm = nm;
        }
        g_pm[n * 64 + blockIdx.x] = bm;
        g_pl[n * 64 + blockIdx.x] = bl;
    }
}

// ---------------- K4: tiny stats reduce per head ---------------------------
// grid NH, block 64
__global__ void __launch_bounds__(64) k_stats() {
    int n = blockIdx.x;
    int t = threadIdx.x;
    __shared__ float sm_m[64], sm_l[64];
    sm_m[t] = g_pm[n * 64 + t];
    sm_l[t] = g_pl[n * 64 + t];
    __syncthreads();
    for (int o = 32; o; o >>= 1) {
        if (t < o) {
            float m2 = sm_m[t + o], l2 = sm_l[t + o];
            float nm = fmaxf(sm_m[t], m2);
            sm_l[t] = sm_l[t] * __expf(sm_m[t] - nm) + l2 * __expf(m2 - nm);
            sm_m[t] = nm;
        }
        __syncthreads();
    }
    if (t == 0) {
        g_mx[n] = sm_m[0];
        g_inv[n] = 1.f / sm_l[0];
    }
}

// ---------------- K5: encoded partials + v-cache copy ----------------------
// grid (32 s-chunks of 128, NH), block 256 = 8 warps; warp handles 16 s rows
__global__ void __launch_bounds__(256) k_enc_partial(const float* __restrict__ v_in,
                                                     const int* __restrict__ tsp,
                                                     float* __restrict__ v_out) {
    int c = blockIdx.x;
    int n = blockIdx.y;
    int warp = threadIdx.x >> 5;
    int lane = threadIdx.x & 31;
    int ts = tsp[0];
    float mx = g_mx[n], inv = g_inv[n];
    const float* lg = g_logits + (size_t)n * S;

    float4 acc = make_float4(0.f, 0.f, 0.f, 0.f);
    int s0 = c * 128 + warp;
#pragma unroll 8
    for (int i = 0; i < 16; ++i) {
        int s = s0 + i * 8;
        size_t ridx = (((size_t)s * NH + n) * H) >> 2;
        float4 vv;
        if (s == ts) {
            vv = ((const float4*)g_vnew)[n * 32 + lane];
        } else {
            vv = ((const float4*)v_in)[ridx + lane];
            ((float4*)v_out)[ridx + lane] = vv;
        }
        float p = __expf(lg[s] - mx) * inv;
        acc.x += p * vv.x; acc.y += p * vv.y;
        acc.z += p * vv.z; acc.w += p * vv.w;
    }

    __shared__ float4 red[8][32];
    red[warp][lane] = acc;
    __syncthreads();
    if (warp == 0) {
        float4 t = red[0][lane];
#pragma unroll
        for (int w = 1; w < 8; ++w) {
            float4 o = red[w][lane];
            t.x += o.x; t.y += o.y; t.z += o.z; t.w += o.w;
        }
        ((float4*)g_encpart)[((size_t)c * NH + n) * 32 + lane] = t;
    }
}

// ---------------- K6: output GEMV partials (fused enc reduce) --------------
// grid (8 d-tiles of 512, 64 nh-chunks of 64), block 128: thread owns 4 d
__global__ void __launch_bounds__(128) k_out_gemv(const float* __restrict__ w_out) {
    __shared__ float enc_s[64];
    int tid = threadIdx.x;
    int nh0 = blockIdx.y * 64;
    if (tid < 64) {
        float v = 0.f;
#pragma unroll
        for (int c = 0; c < 32; ++c) v += g_encpart[(size_t)c * NH * H + nh0 + tid];
        enc_s[tid] = v;
    }
    __syncthreads();

    int d4 = blockIdx.x * 128 + tid;             // float4 index over d
    const float4* wv = (const float4*)w_out;
    float4 acc = make_float4(0.f, 0.f, 0.f, 0.f);
#pragma unroll 8
    for (int j = 0; j < 64; ++j) {
        float e = enc_s[j];
        float4 w4 = wv[(size_t)(nh0 + j) * (D / 4) + d4];
        acc.x += e * w4.x; acc.y += e * w4.y;
        acc.z += e * w4.z; acc.w += e * w4.w;
    }
    ((float4*)g_opart)[(size_t)blockIdx.y * (D / 4) + d4] = acc;
}

// ---------------- K7: final output reduce ----------------------------------
__global__ void __launch_bounds__(128) k_out_reduce(float* __restrict__ attn) {
    int d = blockIdx.x * 128 + threadIdx.x;
    float v = 0.f;
#pragma unroll
    for (int c = 0; c < 64; ++c) v += g_opart[(size_t)c * D + d];
    attn[d] = v;
}

// ---------------- launch ----------------------------------------------------
extern "C" void kernel_launch(void* const* d_in, const int* in_sizes, int n_in,
                              void* d_out, int out_size) {
    const float* x      = (const float*)d_in[0];
    const float* w_qkv  = (const float*)d_in[1];
    const float* w_out  = (const float*)d_in[2];
    const float* k_in   = (const float*)d_in[3];
    const float* v_in   = (const float*)d_in[4];
    const float* mask   = (const float*)d_in[5];
    const int*   segp   = (const int*)d_in[6];
    const int*   tsp    = (const int*)d_in[7];

    float* out   = (float*)d_out;
    float* k_out = out;
    float* v_out = out + (size_t)S * NH * H;
    float* attn  = out + 2ull * S * NH * H;

    k_qkv_partial<<<dim3(96, 16), 128>>>(x, w_qkv);
    k_qkv_rope<<<96, 128>>>(segp, tsp, k_out, v_out);
    k_logits_kcopy<<<dim3(S / 64, NH), 256>>>(k_in, mask, tsp, k_out);
    k_stats<<<NH, 64>>>();
    k_enc_partial<<<dim3(32, NH), 256>>>(v_in, tsp, v_out);
    k_out_gemv<<<dim3(8, 64), 128>>>(w_out);
    k_out_reduce<<<32, 128>>>(attn);
}